// round 13
// baseline (speedup 1.0000x reference)
#include <cuda_runtime.h>

#define BATCH 4096
#define FEAT 40960
#define H1 256
#define CAP 256        // max nonzeros buffered per row (actual data has <=30)
#define NTILES (FEAT / 32 * H1 / 32)   // 10240 transpose tiles (32x32)
#define JTILES (FEAT / 32)             // 1280
#define TCHUNK 16
#define GATE 2048      // only bids < GATE participate in transpose stealing

// Scratch (no allocation allowed)
__device__ __align__(128) float g_ftw_t[(size_t)FEAT * H1];  // 42 MB, [feature][h]
__device__ __align__(128) float g_x[(size_t)BATCH * 2 * H1]; // 8 MB,  [row][512]

// Work-stealing / completion counters (self-resetting each run)
__device__ int g_claim = 0;
__device__ int g_done  = 0;
__device__ int g_fin   = 0;
__device__ int g_row_done[BATCH];   // zero-init; reset by the consumer block

// Streaming float4 load: evict-first (read-once data; don't displace the table)
__device__ __forceinline__ float4 ld_stream_f4(const float4* p) {
    float4 v;
    asm volatile("ld.global.cs.v4.f32 {%0,%1,%2,%3}, [%4];"
                 : "=f"(v.x), "=f"(v.y), "=f"(v.z), "=f"(v.w) : "l"(p));
    return v;
}
// L2-coherent float4 load (bypass L1) for cross-block g_x reads
__device__ __forceinline__ float4 ld_cg_f4(const float4* p) {
    float4 v;
    asm volatile("ld.global.cg.v4.f32 {%0,%1,%2,%3}, [%4];"
                 : "=f"(v.x), "=f"(v.y), "=f"(v.z), "=f"(v.w) : "l"(p));
    return v;
}
// L2-coherent scalar poll (no atomic RMW serialization)
__device__ __forceinline__ int ld_cg_s32(const int* p) {
    int v;
    asm volatile("ld.global.cg.s32 %0, [%1];" : "=r"(v) : "l"(p));
    return v;
}
// Table gather: 32B load with L2 evict_last (sticky)
struct F8 { float f[8]; };
__device__ __forceinline__ F8 ld_table_f8(const float* p) {
    unsigned long long a, b, c, d;
    asm volatile("ld.global.nc.L2::evict_last.v4.b64 {%0,%1,%2,%3}, [%4];"
                 : "=l"(a), "=l"(b), "=l"(c), "=l"(d) : "l"(p));
    F8 r;
    r.f[0] = __uint_as_float((unsigned)a); r.f[1] = __uint_as_float((unsigned)(a >> 32));
    r.f[2] = __uint_as_float((unsigned)b); r.f[3] = __uint_as_float((unsigned)(b >> 32));
    r.f[4] = __uint_as_float((unsigned)c); r.f[5] = __uint_as_float((unsigned)(c >> 32));
    r.f[6] = __uint_as_float((unsigned)d); r.f[7] = __uint_as_float((unsigned)(d >> 32));
    return r;
}

// ---------------------------------------------------------------------------
// Single fused kernel (R8 skeleton): [transpose work-stealing, streaming reads]
// -> scan (single-branch common path) -> wait table (cg poll) -> gather ->
// reduce -> bias+crelu -> g_x -> [second finisher: MLP from smem + L2 partner]
// One block (256 threads = 8 warps) per (row, side) task; grid = 8192.
// ---------------------------------------------------------------------------
__global__ void __launch_bounds__(256) ft_kernel(
    const float* __restrict__ wf, const float* __restrict__ bf,
    const float* __restrict__ ft_w, const float* __restrict__ ft_b,
    const float* __restrict__ fc1_w, const float* __restrict__ fc1_b,
    const float* __restrict__ fc2_w, const float* __restrict__ fc2_b,
    const float* __restrict__ fc3_w, const float* __restrict__ fc3_b,
    float* __restrict__ out)
{
    __shared__ union {
        float tile[32][33];
        float red[8][256];
    } u;
    __shared__ int   s_idx[CAP];
    __shared__ float s_val[CAP];
    __shared__ int   s_count;
    __shared__ int   s_t0;
    __shared__ int   s_do_mlp;
    __shared__ __align__(16) float s_x[512];
    __shared__ __align__(16) float s_y1[32];

    int bid  = blockIdx.x;
    int tid  = threadIdx.x;
    int warp = tid >> 5, lane = tid & 31;

    // ---- Phase 0: transpose work-stealing (streaming reads of ft_w)
    if (bid < GATE) {
        for (;;) {
            if (tid == 0) s_t0 = atomicAdd(&g_claim, TCHUNK);
            __syncthreads();
            int t0 = s_t0;
            if (t0 >= NTILES) break;
            int tend = min(t0 + TCHUNK, NTILES);
            int tx = tid & 7, ty = tid >> 3;
            for (int t = t0; t < tend; t++) {
                int j0 = (t % JTILES) * 32;
                int h0 = (t / JTILES) * 32;
                float4 v = ld_stream_f4((const float4*)&ft_w[(size_t)(h0 + ty) * FEAT + j0 + 4 * tx]);
                u.tile[4 * tx + 0][ty] = v.x;
                u.tile[4 * tx + 1][ty] = v.y;
                u.tile[4 * tx + 2][ty] = v.z;
                u.tile[4 * tx + 3][ty] = v.w;
                __syncthreads();
                float4 o;
                o.x = u.tile[ty][4 * tx + 0];
                o.y = u.tile[ty][4 * tx + 1];
                o.z = u.tile[ty][4 * tx + 2];
                o.w = u.tile[ty][4 * tx + 3];
                *(float4*)&g_ftw_t[(size_t)(j0 + ty) * H1 + h0 + 4 * tx] = o;
                __syncthreads();
            }
            __threadfence();
            if (tid == 0) atomicAdd(&g_done, tend - t0);
        }
    }

    // ---- Phase 1: streaming scan, single branch on the all-zero common path
    int row  = bid >> 1;
    int side = bid & 1;
    const float* feats = side ? bf : wf;
    const float4* frow = (const float4*)(feats + (size_t)row * FEAT);

    if (tid == 0) s_count = 0;
    __syncthreads();

#pragma unroll 8
    for (int i = tid; i < FEAT / 4; i += 256) {
        float4 v = ld_stream_f4(&frow[i]);
        unsigned m = (__float_as_uint(v.x) | __float_as_uint(v.y)) |
                     (__float_as_uint(v.z) | __float_as_uint(v.w));
        if (m != 0u) {   // rare (~30/10240 chunks per row)
            if (v.x != 0.f) { int p = atomicAdd(&s_count, 1); if (p < CAP) { s_idx[p] = 4 * i;     s_val[p] = v.x; } }
            if (v.y != 0.f) { int p = atomicAdd(&s_count, 1); if (p < CAP) { s_idx[p] = 4 * i + 1; s_val[p] = v.y; } }
            if (v.z != 0.f) { int p = atomicAdd(&s_count, 1); if (p < CAP) { s_idx[p] = 4 * i + 2; s_val[p] = v.z; } }
            if (v.w != 0.f) { int p = atomicAdd(&s_count, 1); if (p < CAP) { s_idx[p] = 4 * i + 3; s_val[p] = v.w; } }
        }
    }

    // ---- Barrier: table complete before gathering (cg-read poll)
    if (tid == 0) {
        while (ld_cg_s32(&g_done) < NTILES) { }
    }
    __syncthreads();

    int n = min(s_count, CAP);

    // ---- Phase 2: gather
    float acc[8];
#pragma unroll
    for (int j = 0; j < 8; j++) acc[j] = 0.f;

    for (int k = warp; k < n; k += 8) {
        float v = s_val[k];
        F8 t = ld_table_f8(&g_ftw_t[(size_t)s_idx[k] * H1 + lane * 8]);
#pragma unroll
        for (int j = 0; j < 8; j++) acc[j] = fmaf(v, t.f[j], acc[j]);
    }

#pragma unroll
    for (int j = 0; j < 8; j++) u.red[warp][lane * 8 + j] = acc[j];
    __syncthreads();

    float r = ft_b[tid];
#pragma unroll
    for (int w = 0; w < 8; w++) r += u.red[w][tid];
    r = fminf(fmaxf(r, 0.f), 1.f);
    g_x[(size_t)row * 512 + side * 256 + tid] = r;
    s_x[side * 256 + tid] = r;   // own half stays in smem for the MLP

    // ---- Release our half, trigger per-row MLP on second finisher
    __threadfence();
    __syncthreads();
    if (tid == 0) {
        int old = atomicAdd(&g_row_done[row], 1);
        s_do_mlp = (old == 1);
        if (old == 1) g_row_done[row] = 0;   // reset for next graph replay
    }
    __syncthreads();

    if (s_do_mlp) {
        // Pull ONLY the partner's half from L2 into smem (64 x float4).
        int other = side ^ 1;
        if (tid < 64) {
            float4 x = ld_cg_f4((const float4*)(g_x + (size_t)row * 512 + other * 256) + tid);
            *(float4*)&s_x[other * 256 + 4 * tid] = x;
        }
        __syncthreads();

        // fc1: thread t -> h = t>>3 (0..31), slice = t&7; acts from smem.
        int h = tid >> 3, sl = tid & 7;
        const float4* wr = (const float4*)(fc1_w) + h * 128;
        float p = 0.f;
#pragma unroll
        for (int k = 0; k < 16; k++) {
            int j4 = sl + 8 * k;
            float4 w = __ldg(&wr[j4]);
            p = fmaf(w.x, s_x[4 * j4 + 0], p);
            p = fmaf(w.y, s_x[4 * j4 + 1], p);
            p = fmaf(w.z, s_x[4 * j4 + 2], p);
            p = fmaf(w.w, s_x[4 * j4 + 3], p);
        }
        p += __shfl_xor_sync(0xffffffffu, p, 1);
        p += __shfl_xor_sync(0xffffffffu, p, 2);
        p += __shfl_xor_sync(0xffffffffu, p, 4);
        if (sl == 0)
            s_y1[h] = fminf(fmaxf(p + __ldg(&fc1_b[h]), 0.f), 1.f);
        __syncthreads();

        if (tid < 32) {
            float y2 = __ldg(&fc2_b[tid]);
#pragma unroll
            for (int j = 0; j < 32; j++)
                y2 = fmaf(__ldg(&fc2_w[tid * 32 + j]), s_y1[j], y2);
            y2 = fminf(fmaxf(y2, 0.f), 1.f);
            float p3 = __ldg(&fc3_w[tid]) * y2;
#pragma unroll
            for (int o = 16; o; o >>= 1) p3 += __shfl_xor_sync(0xffffffffu, p3, o);
            if (tid == 0) out[row] = p3 + __ldg(&fc3_b[0]);
        }
    }

    // ---- Reset shared counters (last block)
    __syncthreads();
    if (tid == 0) {
        int f = atomicAdd(&g_fin, 1);
        if (f == 2 * BATCH - 1) {
            g_claim = 0; g_done = 0; g_fin = 0;
            __threadfence();
        }
    }
}

// ---------------------------------------------------------------------------
extern "C" void kernel_launch(void* const* d_in, const int* in_sizes, int n_in,
                              void* d_out, int out_size) {
    const float* wf    = (const float*)d_in[0];
    const float* bf    = (const float*)d_in[1];
    const float* ft_w  = (const float*)d_in[2];
    const float* ft_b  = (const float*)d_in[3];
    const float* fc1_w = (const float*)d_in[4];
    const float* fc1_b = (const float*)d_in[5];
    const float* fc2_w = (const float*)d_in[6];
    const float* fc2_b = (const float*)d_in[7];
    const float* fc3_w = (const float*)d_in[8];
    const float* fc3_b = (const float*)d_in[9];
    float* out = (float*)d_out;

    ft_kernel<<<2 * BATCH, 256>>>(wf, bf, ft_w, ft_b,
                                  fc1_w, fc1_b, fc2_w, fc2_b, fc3_w, fc3_b, out);
}

// round 15
// speedup vs baseline: 1.1172x; 1.1172x over previous
#include <cuda_runtime.h>

#define BATCH 4096
#define FEAT 40960
#define H1 256
#define CAP 256        // max nonzeros buffered per row (actual data has <=30)
#define NTILES (FEAT / 32 * H1 / 32)   // 10240 transpose tiles (32x32)
#define JTILES (FEAT / 32)             // 1280
#define TCHUNK 16
#define GATE 2048      // only bids < GATE participate in transpose stealing

// Scratch (no allocation allowed)
__device__ __align__(128) float g_ftw_t[(size_t)FEAT * H1];  // 42 MB, [feature][h]
__device__ __align__(128) float g_x[(size_t)BATCH * 2 * H1]; // 8 MB,  [row][512]

// Work-stealing / completion counters (self-resetting each run)
__device__ int g_claim = 0;
__device__ int g_done  = 0;
__device__ int g_fin   = 0;
__device__ int g_row_done[BATCH];   // zero-init; reset by the consumer block

// Streaming float4 load: evict-first (don't displace the table in L2)
__device__ __forceinline__ float4 ld_stream_f4(const float4* p) {
    float4 v;
    asm volatile("ld.global.cs.v4.f32 {%0,%1,%2,%3}, [%4];"
                 : "=f"(v.x), "=f"(v.y), "=f"(v.z), "=f"(v.w) : "l"(p));
    return v;
}
// L2-coherent float4 load (bypass L1) for cross-block g_x reads
__device__ __forceinline__ float4 ld_cg_f4(const float4* p) {
    float4 v;
    asm volatile("ld.global.cg.v4.f32 {%0,%1,%2,%3}, [%4];"
                 : "=f"(v.x), "=f"(v.y), "=f"(v.z), "=f"(v.w) : "l"(p));
    return v;
}
// L2-coherent scalar poll (no atomic RMW serialization)
__device__ __forceinline__ int ld_cg_s32(const int* p) {
    int v;
    asm volatile("ld.global.cg.s32 %0, [%1];" : "=r"(v) : "l"(p));
    return v;
}
// Table gather: 32B L2-COHERENT load. The table is written earlier in this
// same launch, so the .nc (read-only) path is illegal — cg reads from L2,
// the coherence point, after the release-fenced publish.
struct F8 { float f[8]; };
__device__ __forceinline__ F8 ld_table_f8(const float* p) {
    unsigned long long a, b, c, d;
    asm volatile("ld.global.cg.v4.b64 {%0,%1,%2,%3}, [%4];"
                 : "=l"(a), "=l"(b), "=l"(c), "=l"(d) : "l"(p));
    F8 r;
    r.f[0] = __uint_as_float((unsigned)a); r.f[1] = __uint_as_float((unsigned)(a >> 32));
    r.f[2] = __uint_as_float((unsigned)b); r.f[3] = __uint_as_float((unsigned)(b >> 32));
    r.f[4] = __uint_as_float((unsigned)c); r.f[5] = __uint_as_float((unsigned)(c >> 32));
    r.f[6] = __uint_as_float((unsigned)d); r.f[7] = __uint_as_float((unsigned)(d >> 32));
    return r;
}

// ---------------------------------------------------------------------------
// Single fused kernel (R12 skeleton): [transpose work-stealing] -> scan ->
// wait table (cg poll) -> gather (cg, coherent) -> reduce -> bias+crelu ->
// g_x -> [second finisher per row: MLP from smem(own half) + L2(partner half)]
// One block (256 threads = 8 warps) per (row, side) task; grid = 8192.
// ---------------------------------------------------------------------------
__global__ void __launch_bounds__(256) ft_kernel(
    const float* __restrict__ wf, const float* __restrict__ bf,
    const float* __restrict__ ft_w, const float* __restrict__ ft_b,
    const float* __restrict__ fc1_w, const float* __restrict__ fc1_b,
    const float* __restrict__ fc2_w, const float* __restrict__ fc2_b,
    const float* __restrict__ fc3_w, const float* __restrict__ fc3_b,
    float* __restrict__ out)
{
    __shared__ union {
        float tile[32][33];
        float red[8][256];
    } u;
    __shared__ int   s_idx[CAP];
    __shared__ float s_val[CAP];
    __shared__ int   s_count;
    __shared__ int   s_t0;
    __shared__ int   s_do_mlp;
    __shared__ __align__(16) float s_x[512];
    __shared__ __align__(16) float s_y1[32];

    int bid  = blockIdx.x;
    int tid  = threadIdx.x;
    int warp = tid >> 5, lane = tid & 31;

    // ---- Phase 0: transpose work-stealing
    if (bid < GATE) {
        for (;;) {
            if (tid == 0) s_t0 = atomicAdd(&g_claim, TCHUNK);
            __syncthreads();
            int t0 = s_t0;
            if (t0 >= NTILES) break;
            int tend = min(t0 + TCHUNK, NTILES);
            int tx = tid & 7, ty = tid >> 3;
            for (int t = t0; t < tend; t++) {
                int j0 = (t % JTILES) * 32;
                int h0 = (t / JTILES) * 32;
                float4 v = *(const float4*)&ft_w[(size_t)(h0 + ty) * FEAT + j0 + 4 * tx];
                u.tile[4 * tx + 0][ty] = v.x;
                u.tile[4 * tx + 1][ty] = v.y;
                u.tile[4 * tx + 2][ty] = v.z;
                u.tile[4 * tx + 3][ty] = v.w;
                __syncthreads();
                float4 o;
                o.x = u.tile[ty][4 * tx + 0];
                o.y = u.tile[ty][4 * tx + 1];
                o.z = u.tile[ty][4 * tx + 2];
                o.w = u.tile[ty][4 * tx + 3];
                *(float4*)&g_ftw_t[(size_t)(j0 + ty) * H1 + h0 + 4 * tx] = o;
                __syncthreads();
            }
            __threadfence();   // release: table writes visible at L2 before count
            if (tid == 0) atomicAdd(&g_done, tend - t0);
        }
    }

    // ---- Phase 1: streaming scan (R12-verbatim — DO NOT TOUCH)
    int row  = bid >> 1;
    int side = bid & 1;
    const float* feats = side ? bf : wf;
    const float4* frow = (const float4*)(feats + (size_t)row * FEAT);

    if (tid == 0) s_count = 0;
    __syncthreads();

#pragma unroll 8
    for (int i = tid; i < FEAT / 4; i += 256) {
        float4 v = ld_stream_f4(&frow[i]);
        if (v.x != 0.f) { int p = atomicAdd(&s_count, 1); if (p < CAP) { s_idx[p] = 4 * i;     s_val[p] = v.x; } }
        if (v.y != 0.f) { int p = atomicAdd(&s_count, 1); if (p < CAP) { s_idx[p] = 4 * i + 1; s_val[p] = v.y; } }
        if (v.z != 0.f) { int p = atomicAdd(&s_count, 1); if (p < CAP) { s_idx[p] = 4 * i + 2; s_val[p] = v.z; } }
        if (v.w != 0.f) { int p = atomicAdd(&s_count, 1); if (p < CAP) { s_idx[p] = 4 * i + 3; s_val[p] = v.w; } }
    }

    // ---- Barrier: table complete before gathering (cg-read poll at L2)
    if (tid == 0) {
        while (ld_cg_s32(&g_done) < NTILES) { }
    }
    __syncthreads();

    int n = min(s_count, CAP);

    // ---- Phase 2: gather (coherent cg loads from L2-resident table)
    float acc[8];
#pragma unroll
    for (int j = 0; j < 8; j++) acc[j] = 0.f;

    for (int k = warp; k < n; k += 8) {
        float v = s_val[k];
        F8 t = ld_table_f8(&g_ftw_t[(size_t)s_idx[k] * H1 + lane * 8]);
#pragma unroll
        for (int j = 0; j < 8; j++) acc[j] = fmaf(v, t.f[j], acc[j]);
    }

#pragma unroll
    for (int j = 0; j < 8; j++) u.red[warp][lane * 8 + j] = acc[j];
    __syncthreads();

    float r = ft_b[tid];
#pragma unroll
    for (int w = 0; w < 8; w++) r += u.red[w][tid];
    r = fminf(fmaxf(r, 0.f), 1.f);
    g_x[(size_t)row * 512 + side * 256 + tid] = r;
    s_x[side * 256 + tid] = r;   // own half stays in smem for the MLP

    // ---- Release our half, trigger per-row MLP on second finisher
    __threadfence();
    __syncthreads();
    if (tid == 0) {
        int old = atomicAdd(&g_row_done[row], 1);
        s_do_mlp = (old == 1);
        if (old == 1) g_row_done[row] = 0;   // reset for next graph replay
    }
    __syncthreads();

    if (s_do_mlp) {
        // Pull ONLY the partner's half from L2 into smem (64 x float4).
        int other = side ^ 1;
        if (tid < 64) {
            float4 x = ld_cg_f4((const float4*)(g_x + (size_t)row * 512 + other * 256) + tid);
            *(float4*)&s_x[other * 256 + 4 * tid] = x;
        }
        __syncthreads();

        // fc1: thread t -> h = t>>3 (0..31), slice = t&7; acts from smem.
        int h = tid >> 3, sl = tid & 7;
        const float4* wr = (const float4*)(fc1_w) + h * 128;
        float p = 0.f;
#pragma unroll
        for (int k = 0; k < 16; k++) {
            int j4 = sl + 8 * k;
            float4 w = __ldg(&wr[j4]);
            p = fmaf(w.x, s_x[4 * j4 + 0], p);
            p = fmaf(w.y, s_x[4 * j4 + 1], p);
            p = fmaf(w.z, s_x[4 * j4 + 2], p);
            p = fmaf(w.w, s_x[4 * j4 + 3], p);
        }
        p += __shfl_xor_sync(0xffffffffu, p, 1);
        p += __shfl_xor_sync(0xffffffffu, p, 2);
        p += __shfl_xor_sync(0xffffffffu, p, 4);
        if (sl == 0)
            s_y1[h] = fminf(fmaxf(p + __ldg(&fc1_b[h]), 0.f), 1.f);
        __syncthreads();

        if (tid < 32) {
            float y2 = __ldg(&fc2_b[tid]);
#pragma unroll
            for (int j = 0; j < 32; j++)
                y2 = fmaf(__ldg(&fc2_w[tid * 32 + j]), s_y1[j], y2);
            y2 = fminf(fmaxf(y2, 0.f), 1.f);
            float p3 = __ldg(&fc3_w[tid]) * y2;
#pragma unroll
            for (int o = 16; o; o >>= 1) p3 += __shfl_xor_sync(0xffffffffu, p3, o);
            if (tid == 0) out[row] = p3 + __ldg(&fc3_b[0]);
        }
    }

    // ---- Reset shared counters (last block)
    __syncthreads();
    if (tid == 0) {
        int f = atomicAdd(&g_fin, 1);
        if (f == 2 * BATCH - 1) {
            g_claim = 0; g_done = 0; g_fin = 0;
            __threadfence();
        }
    }
}

// ---------------------------------------------------------------------------
extern "C" void kernel_launch(void* const* d_in, const int* in_sizes, int n_in,
                              void* d_out, int out_size) {
    const float* wf    = (const float*)d_in[0];
    const float* bf    = (const float*)d_in[1];
    const float* ft_w  = (const float*)d_in[2];
    const float* ft_b  = (const float*)d_in[3];
    const float* fc1_w = (const float*)d_in[4];
    const float* fc1_b = (const float*)d_in[5];
    const float* fc2_w = (const float*)d_in[6];
    const float* fc2_b = (const float*)d_in[7];
    const float* fc3_w = (const float*)d_in[8];
    const float* fc3_b = (const float*)d_in[9];
    float* out = (float*)d_out;

    ft_kernel<<<2 * BATCH, 256>>>(wf, bf, ft_w, ft_b,
                                  fc1_w, fc1_b, fc2_w, fc2_b, fc3_w, fc3_b, out);
}